// round 3
// baseline (speedup 1.0000x reference)
#include <cuda_runtime.h>

// Guided_Conv: 4096 independent 24x24x9 patches.
// patch n = b*256 + i*16 + j  (b=batch, i=patch-row, j=patch-col)
//   input  pixel (pr,pc,f): guidance/depth[ ((b*384 + i*24+pr)*384 + j*24+pc)*9 + f ]
//   output pixel (pr,pc,f): out[ n*5184 + (pr*24+pc)*9 + f ]   (contiguous block per patch)

#define NPIX   576            // 24*24
#define THREADS 576
#define ROW_F4 54             // 24*9/4 float4 per patch row
#define ROWSTRIDE4 864        // 384*9/4 float4 per image row

// Depth tile with zero halo: 26x26 pixels, 9 ch, row stride padded to 236 floats
// so each interior row start (236*p + 248) is float4-aligned.
// pixel (pp,qq) in [-1,24]^2 lives at  3 + 236*(pp+1) + 9*(qq+1).
#define DPAD_FLOATS 6140      // 3 + 236*26, rounded to /4
#define DPAD_F4     1535

__global__ __launch_bounds__(THREADS, 3)
void guided_conv_kernel(const float* __restrict__ guidance,
                        const float* __restrict__ depth,
                        const float* __restrict__ conv_w,   // (3,3,9,9)
                        const float* __restrict__ conv_b,   // (9,)
                        const float* __restrict__ dense_w,  // (9,81)
                        const float* __restrict__ dense_b,  // (81,)
                        float* __restrict__ out)
{
    __shared__ __align__(16) float g_s[NPIX * 9];    // guidance patch, later OUTPUT staging
    __shared__ __align__(16) float d_pad[DPAD_FLOATS]; // depth patch, zero halo
    __shared__ float cw_s[729];                      // conv_w
    __shared__ float dw_s[729];                      // dense_w
    __shared__ float cb_s[9];
    __shared__ float db_s[81];
    __shared__ float c_s[81];                        // conv out [k=ky*3+kx][o]
    __shared__ float gap_s[9];
    __shared__ float dvec_s[81];                     // dense out [i][o]
    __shared__ float w1_s[81];                       // normalized depthwise kernel [k][f]
    __shared__ float w2_s[81];                       // normalized mix [i][o]

    const int n   = blockIdx.x;
    const int b   = n >> 8;
    const int pi  = (n >> 4) & 15;
    const int pj  = n & 15;
    const int tid = threadIdx.x;

    // ---- Phase 1: stage patches + weights, zero halo (disjoint writes, no race) ----
    const int base4 = (((b * 384 + pi * 24) * 384 + pj * 24) * 9) >> 2;
    const float4* g4 = reinterpret_cast<const float4*>(guidance);
    const float4* d4 = reinterpret_cast<const float4*>(depth);
    float4* gs4 = reinterpret_cast<float4*>(g_s);
    float4* dp4 = reinterpret_cast<float4*>(d_pad);

    // zero the 955 halo floats (as 239 float4 slots; interior slots untouched)
    if (tid < 239) {
        int f4i;
        if (tid < 62)       f4i = tid;                                   // [0,248) floats
        else if (tid < 177) { int z = tid - 62; f4i = 59 * (z / 5) + 116 + (z % 5); } // row gaps
        else                f4i = 1473 + (tid - 177);                    // [5892,6140)
        dp4[f4i] = make_float4(0.f, 0.f, 0.f, 0.f);
    }

    for (int idx = tid; idx < 24 * ROW_F4; idx += THREADS) {
        const int pr = idx / ROW_F4;
        const int c4 = idx - pr * ROW_F4;
        const int gi = base4 + pr * ROWSTRIDE4 + c4;
        gs4[idx] = g4[gi];
        dp4[59 * pr + 62 + c4] = d4[gi];   // interior row pr, float4-aligned
    }
    for (int idx = tid; idx < 729; idx += THREADS) {
        cw_s[idx] = conv_w[idx];
        dw_s[idx] = dense_w[idx];
    }
    if (tid < 81) db_s[tid] = dense_b[tid];
    if (tid >= 96 && tid < 105) cb_s[tid - 96] = conv_b[tid - 96];
    __syncthreads();

    // ---- Phase 2: two independent weight chains on disjoint warp groups ----
    if (tid < 96) {
        // warps 0-2: strided conv -> per-channel clip-by-norm -> w1
        if (tid < 81) {
            const int o  = tid % 9;
            const int k  = tid / 9;
            const int ky = k / 3, kx = k % 3;
            float acc = cb_s[o];
            #pragma unroll
            for (int r = 0; r < 3; r++) {
                #pragma unroll
                for (int s = 0; s < 3; s++) {
                    const float* gp = &g_s[((8 * ky + r) * 24 + 8 * kx + s) * 9];
                    const float* wp = &cw_s[((r * 3 + s) * 9) * 9 + o];
                    #pragma unroll
                    for (int ii = 0; ii < 9; ii++)
                        acc += gp[ii] * wp[ii * 9];
                }
            }
            c_s[k * 9 + o] = acc;
        }
        asm volatile("bar.sync 1, 96;" ::: "memory");
        if (tid < 9) {
            const int o = tid;
            float ss = 0.f;
            #pragma unroll
            for (int k = 0; k < 9; k++) { const float v = c_s[k * 9 + o]; ss += v * v; }
            const float scale = 1.0f / fmaxf(sqrtf(ss), 1.0f);
            #pragma unroll
            for (int k = 0; k < 9; k++) w1_s[k * 9 + o] = c_s[k * 9 + o] * scale;
        }
    } else if (tid < 384) {
        // warps 3-11: patch mean -> dense -> per-column clip-by-norm -> w2
        {
            const int f    = (tid - 96) >> 5;
            const int lane = tid & 31;
            float s = 0.f;
            #pragma unroll
            for (int p = 0; p < 18; p++)
                s += g_s[(lane + 32 * p) * 9 + f];   // lane stride 9 -> conflict-free
            #pragma unroll
            for (int off = 16; off > 0; off >>= 1)
                s += __shfl_down_sync(0xffffffffu, s, off);
            if (lane == 0) gap_s[f] = s * (1.0f / 576.0f);
        }
        asm volatile("bar.sync 2, 288;" ::: "memory");
        if (tid < 177) {
            const int j = tid - 96;                  // 81 threads
            float acc = db_s[j];
            #pragma unroll
            for (int ii = 0; ii < 9; ii++)
                acc += gap_s[ii] * dw_s[ii * 81 + j];
            dvec_s[j] = acc;
        }
        asm volatile("bar.sync 2, 288;" ::: "memory");
        if (tid < 105) {
            const int o = tid - 96;                  // 9 threads
            float ss = 0.f;
            #pragma unroll
            for (int ii = 0; ii < 9; ii++) { const float v = dvec_s[ii * 9 + o]; ss += v * v; }
            const float scale = 1.0f / fmaxf(sqrtf(ss), 1.0f);
            #pragma unroll
            for (int ii = 0; ii < 9; ii++) w2_s[ii * 9 + o] = dvec_s[ii * 9 + o] * scale;
        }
    }
    __syncthreads();

    // ---- Phase 5: branch-free depthwise 3x3 (zero halo) + 9x9 channel mix ----
    const int p = tid / 24;
    const int q = tid - p * 24;
    const float* dbse = d_pad + 3 + 236 * p + 9 * q;   // pixel (p-1,q-1); offsets 236*dy+9*dx+ii

    float dc[9];
    #pragma unroll
    for (int ii = 0; ii < 9; ii++) dc[ii] = 0.f;

    #pragma unroll
    for (int dy = 0; dy < 3; dy++) {
        #pragma unroll
        for (int dx = 0; dx < 3; dx++) {
            const float* dp = dbse + 236 * dy + 9 * dx;
            const float* wp = &w1_s[(dy * 3 + dx) * 9];   // broadcast
            #pragma unroll
            for (int ii = 0; ii < 9; ii++)
                dc[ii] += dp[ii] * wp[ii];
        }
    }

    // mix channels, stage into g_s (dead after phase 2): [pix][f] = output patch layout
    #pragma unroll
    for (int o = 0; o < 9; o++) {
        float acc = 0.f;
        #pragma unroll
        for (int ii = 0; ii < 9; ii++)
            acc += dc[ii] * w2_s[ii * 9 + o];             // broadcast
        g_s[tid * 9 + o] = acc;                           // stride 9 -> conflict-free
    }
    __syncthreads();

    // ---- Phase 6: coalesced float4 store of the whole patch ----
    const float4* src = reinterpret_cast<const float4*>(g_s);
    float4* dst = reinterpret_cast<float4*>(out + (size_t)n * 5184);
    #pragma unroll 3
    for (int idx = tid; idx < 1296; idx += THREADS)
        dst[idx] = src[idx];
}

extern "C" void kernel_launch(void* const* d_in, const int* in_sizes, int n_in,
                              void* d_out, int out_size) {
    const float* guidance = (const float*)d_in[0];
    const float* depth    = (const float*)d_in[1];
    const float* conv_w   = (const float*)d_in[2];
    const float* conv_b   = (const float*)d_in[3];
    const float* dense_w  = (const float*)d_in[4];
    const float* dense_b  = (const float*)d_in[5];
    float* out = (float*)d_out;

    guided_conv_kernel<<<4096, THREADS>>>(guidance, depth, conv_w, conv_b,
                                          dense_w, dense_b, out);
}

// round 4
// speedup vs baseline: 1.2733x; 1.2733x over previous
#include <cuda_runtime.h>

// Guided_Conv: 4096 independent 24x24x9 patches.
// patch n = b*256 + i*16 + j  (b=batch, i=patch-row, j=patch-col)
//   input  pixel (pr,pc,f): guidance/depth[ ((b*384 + i*24+pr)*384 + j*24+pc)*9 + f ]
//   output pixel (pr,pc,f): out[ n*5184 + (pr*24+pc)*9 + f ]   (contiguous block per patch)

#define NPIX   576            // 24*24
#define THREADS 576
#define ROW_F4 54             // 24*9/4 float4 per patch row
#define ROWSTRIDE4 864        // 384*9/4 float4 per image row

// Channel-planar depth tile with zero halo:
//   plane f holds 26x26 single-channel pixels, row stride 40 floats.
//   pixel (pp,qq), pp,qq in [-1,24], lives at f*PS + (pp+1)*40 + (qq+1).
// Row stride 40 => depthwise warp loads (fixed f; br 0..7, bc 0..7) hit banks
// (120*br + 3*bc) mod 32 = (24*br + 3*bc) mod 32: all 32 distinct (conflict-free).
#define DROW 40
#define DPS  1041             // plane stride (odd -> scatter stores spread banks)
#define DPLANAR_FLOATS (DPS * 9)

__global__ __launch_bounds__(THREADS, 3)
void guided_conv_kernel(const float* __restrict__ guidance,
                        const float* __restrict__ depth,
                        const float* __restrict__ conv_w,   // (3,3,9,9)
                        const float* __restrict__ conv_b,   // (9,)
                        const float* __restrict__ dense_w,  // (9,81)
                        const float* __restrict__ dense_b,  // (81,)
                        float* __restrict__ out)
{
    __shared__ __align__(16) float g_s[NPIX * 9];          // guidance patch -> dc buffer
    __shared__ __align__(16) float d_planar[DPLANAR_FLOATS]; // planar depth -> output staging
    __shared__ float cw_s[729];                            // conv_w
    __shared__ float dw_s[729];                            // dense_w
    __shared__ float cb_s[9];
    __shared__ float db_s[81];
    __shared__ float c_s[81];                              // conv out [k][o]
    __shared__ float gap_s[9];
    __shared__ float dvec_s[81];                           // dense out [i][o]
    __shared__ float w1_s[81];                             // depthwise kernel [k][f]
    __shared__ float w2_s[81];                             // channel mix [i][o]

    const int n   = blockIdx.x;
    const int b   = n >> 8;
    const int pi  = (n >> 4) & 15;
    const int pj  = n & 15;
    const int tid = threadIdx.x;

    // ---- Phase 1: stage guidance (float4), depth (planar scatter), weights ----
    // Zero only the halo cells of each plane (disjoint from interior writes).
    for (int h = tid; h < 900; h += THREADS) {
        const int f = h / 100;
        const int r = h - f * 100;
        int addr;
        if (r < 26)       addr = r;                        // planar row 0
        else if (r < 52)  addr = 25 * DROW + (r - 26);     // planar row 25
        else if (r < 76)  addr = (r - 52 + 1) * DROW;      // planar col 0
        else              addr = (r - 76 + 1) * DROW + 25; // planar col 25
        d_planar[f * DPS + addr] = 0.f;
    }

    const int base4 = (((b * 384 + pi * 24) * 384 + pj * 24) * 9) >> 2;
    const float4* g4 = reinterpret_cast<const float4*>(guidance);
    const float4* d4 = reinterpret_cast<const float4*>(depth);
    float4* gs4 = reinterpret_cast<float4*>(g_s);

    for (int idx = tid; idx < 24 * ROW_F4; idx += THREADS) {
        const int pr = idx / ROW_F4;
        const int c4 = idx - pr * ROW_F4;
        const int gi = base4 + pr * ROWSTRIDE4 + c4;
        gs4[idx] = g4[gi];
        const float4 dv = d4[gi];
        // scatter 4 floats to channel planes: row float offset t -> (qq=t/9, ch=t%9)
        const int t0 = c4 * 4;
        const float dvs[4] = {dv.x, dv.y, dv.z, dv.w};
        #pragma unroll
        for (int j = 0; j < 4; j++) {
            const int t  = t0 + j;
            const int qq = t / 9;
            const int ch = t - qq * 9;
            d_planar[ch * DPS + (pr + 1) * DROW + (qq + 1)] = dvs[j];
        }
    }
    for (int idx = tid; idx < 729; idx += THREADS) {
        cw_s[idx] = conv_w[idx];
        dw_s[idx] = dense_w[idx];
    }
    if (tid < 81) db_s[tid] = dense_b[tid];
    if (tid >= 96 && tid < 105) cb_s[tid - 96] = conv_b[tid - 96];
    __syncthreads();

    // ---- Phase 2: strided conv (tid<81)  ||  patch mean (warps 3..11) ----
    if (tid < 81) {
        const int o  = tid % 9;
        const int k  = tid / 9;
        const int ky = k / 3, kx = k % 3;
        float acc = cb_s[o];
        #pragma unroll
        for (int r = 0; r < 3; r++) {
            #pragma unroll
            for (int s = 0; s < 3; s++) {
                const float* gp = &g_s[((8 * ky + r) * 24 + 8 * kx + s) * 9];
                const float* wp = &cw_s[((r * 3 + s) * 9) * 9 + o];
                #pragma unroll
                for (int ii = 0; ii < 9; ii++)
                    acc += gp[ii] * wp[ii * 9];
            }
        }
        c_s[k * 9 + o] = acc;
    } else if (tid >= 96 && tid < 384) {
        const int f    = (tid - 96) >> 5;
        const int lane = tid & 31;
        float s = 0.f;
        #pragma unroll
        for (int p = 0; p < 18; p++)
            s += g_s[(lane + 32 * p) * 9 + f];   // lane stride 9 -> conflict-free
        #pragma unroll
        for (int off = 16; off > 0; off >>= 1)
            s += __shfl_down_sync(0xffffffffu, s, off);
        if (lane == 0) gap_s[f] = s * (1.0f / 576.0f);
    }
    __syncthreads();

    // ---- Phase 3: dense (tid<81)  ||  W1 clip-by-norm (tid 96..104) ----
    if (tid < 81) {
        float acc = db_s[tid];
        #pragma unroll
        for (int ii = 0; ii < 9; ii++)
            acc += gap_s[ii] * dw_s[ii * 81 + tid];
        dvec_s[tid] = acc;
    } else if (tid >= 96 && tid < 105) {
        const int o = tid - 96;
        float ss = 0.f;
        #pragma unroll
        for (int k = 0; k < 9; k++) { const float v = c_s[k * 9 + o]; ss += v * v; }
        const float scale = 1.0f / fmaxf(sqrtf(ss), 1.0f);
        #pragma unroll
        for (int k = 0; k < 9; k++) w1_s[k * 9 + o] = c_s[k * 9 + o] * scale;
    }
    __syncthreads();

    // ---- Phase 4: W2 clip-by-norm (per output column, over input dim) ----
    if (tid < 9) {
        const int o = tid;
        float ss = 0.f;
        #pragma unroll
        for (int ii = 0; ii < 9; ii++) { const float v = dvec_s[ii * 9 + o]; ss += v * v; }
        const float scale = 1.0f / fmaxf(sqrtf(ss), 1.0f);
        #pragma unroll
        for (int ii = 0; ii < 9; ii++) w2_s[ii * 9 + o] = dvec_s[ii * 9 + o] * scale;
    }
    __syncthreads();

    // ---- Phase 5a: per-channel depthwise 3x3.  thread = (channel f, 3x3 block)
    //      25 LDS per thread for 9 outputs (2.8 per pixel vs 9 before).
    {
        const int f   = tid >> 6;            // warp covers a single channel
        const int blk = tid & 63;
        const int br  = blk >> 3;
        const int bc  = blk & 7;
        // 5x5 planar window: pixel rows 3br-1..3br+3 = planar rows 3br..3br+4
        const float* plane = d_planar + f * DPS + (3 * br) * DROW + 3 * bc;

        float w1f[9];
        #pragma unroll
        for (int k = 0; k < 9; k++) w1f[k] = w1_s[k * 9 + f];  // broadcast per warp

        float win[15];                        // rolling 3-row x 5-col window
        #pragma unroll
        for (int r = 0; r < 3; r++)
            #pragma unroll
            for (int c = 0; c < 5; c++)
                win[r * 5 + c] = plane[r * DROW + c];

        #pragma unroll
        for (int rp = 0; rp < 3; rp++) {
            #pragma unroll
            for (int cp = 0; cp < 3; cp++) {
                float acc = 0.f;
                #pragma unroll
                for (int dy = 0; dy < 3; dy++)
                    #pragma unroll
                    for (int dx = 0; dx < 3; dx++)
                        acc += w1f[dy * 3 + dx] * win[dy * 5 + cp + dx];
                const int pix = (3 * br + rp) * 24 + 3 * bc + cp;
                g_s[pix * 9 + f] = acc;       // banks (8br+27bc)%32: conflict-free
            }
            if (rp < 2) {
                #pragma unroll
                for (int i = 0; i < 10; i++) win[i] = win[i + 5];
                #pragma unroll
                for (int c = 0; c < 5; c++)
                    win[10 + c] = plane[(rp + 3) * DROW + c];
            }
        }
    }
    __syncthreads();

    // ---- Phase 5b: 9x9 channel mix; stage output into d_planar (dead now) ----
    {
        float dcv[9];
        #pragma unroll
        for (int ii = 0; ii < 9; ii++) dcv[ii] = g_s[tid * 9 + ii];  // conflict-free
        #pragma unroll
        for (int o = 0; o < 9; o++) {
            float acc = 0.f;
            #pragma unroll
            for (int ii = 0; ii < 9; ii++)
                acc += dcv[ii] * w2_s[ii * 9 + o];                   // broadcast
            d_planar[tid * 9 + o] = acc;                             // conflict-free
        }
    }
    __syncthreads();

    // ---- Phase 6: coalesced float4 store of the whole patch ----
    const float4* src = reinterpret_cast<const float4*>(d_planar);
    float4* dst = reinterpret_cast<float4*>(out + (size_t)n * 5184);
    #pragma unroll 3
    for (int idx = tid; idx < 1296; idx += THREADS)
        dst[idx] = src[idx];
}

extern "C" void kernel_launch(void* const* d_in, const int* in_sizes, int n_in,
                              void* d_out, int out_size) {
    const float* guidance = (const float*)d_in[0];
    const float* depth    = (const float*)d_in[1];
    const float* conv_w   = (const float*)d_in[2];
    const float* conv_b   = (const float*)d_in[3];
    const float* dense_w  = (const float*)d_in[4];
    const float* dense_b  = (const float*)d_in[5];
    float* out = (float*)d_out;

    guided_conv_kernel<<<4096, THREADS>>>(guidance, depth, conv_w, conv_b,
                                          dense_w, dense_b, out);
}